// round 1
// baseline (speedup 1.0000x reference)
#include <cuda_runtime.h>
#include <math.h>

// EulerRosenbrockModel: B=512, D=256, HID=1024, H_STEP=0.01
// out = (I - A/3)^{-1} (I + A/6) v,  A = 0.01 * W2 diag(1-tanh^2) W1,  v = f(y)
// Computed matrix-free via Neumann/Horner series (||A/3|| <= ~0.015):
//   w = v + (A/6)v ;  x = w + (A/3)(w + (A/3)(w + (A/3)w))
// Each A-application = GEMM(512x1024,K=256) [epilogue *(1-T^2)] then
//                      GEMM(512x256,K=1024) [epilogue base + c*X]

static constexpr int BATCH = 512;
static constexpr int DIM   = 256;
static constexpr int HID   = 1024;

// scratch (device globals: no allocation allowed)
__device__ float g_T[BATCH * HID];   // tanh(W1 y + b1)
__device__ float g_P[BATCH * HID];   // intermediate (U W1^T) * (1 - T^2)
__device__ float g_V[BATCH * DIM];   // v = f(y)
__device__ float g_W[BATCH * DIM];   // w = v + (A/6)v
__device__ float g_R[BATCH * DIM];   // Horner iterates
__device__ float g_R2[BATCH * DIM];

#define MODE_TANH 0
#define MODE_BIAS 1
#define MODE_MULS 2
#define MODE_AXPY 3

// C[M,N] = A[M,K] * B[N,K]^T  (NT GEMM, both operands K-contiguous), fused epilogue.
template<int BM, int BN, int BK, int TM, int TN, int MODE>
__global__ void __launch_bounds__((BM/TM)*(BN/TN))
gemm_nt(const float* __restrict__ A, const float* __restrict__ Bw,
        float* __restrict__ C, int M, int N, int K,
        const float* __restrict__ bias, const float* __restrict__ tanhT,
        const float* __restrict__ base, float scale)
{
    constexpr int NT  = (BM/TM)*(BN/TN);
    constexpr int LDA = BM + 4;
    constexpr int LDB = BN + 4;
    __shared__ float As[BK][LDA];
    __shared__ float Bs[BK][LDB];

    const int tid = threadIdx.x;
    const int tx  = tid % (BN/TN);
    const int ty  = tid / (BN/TN);
    const int m0  = blockIdx.y * BM;
    const int n0  = blockIdx.x * BN;

    float acc[TM][TN];
    #pragma unroll
    for (int i = 0; i < TM; i++)
        #pragma unroll
        for (int j = 0; j < TN; j++)
            acc[i][j] = 0.0f;

    for (int k0 = 0; k0 < K; k0 += BK) {
        // load A tile (transposed into smem: As[k][m])
        #pragma unroll
        for (int t = tid; t < BM*BK/4; t += NT) {
            int row = t / (BK/4);
            int q   = t % (BK/4);
            float4 v = *(const float4*)(&A[(m0 + row) * K + k0 + q*4]);
            As[q*4+0][row] = v.x;
            As[q*4+1][row] = v.y;
            As[q*4+2][row] = v.z;
            As[q*4+3][row] = v.w;
        }
        // load B tile (transposed into smem: Bs[k][n])
        #pragma unroll
        for (int t = tid; t < BN*BK/4; t += NT) {
            int row = t / (BK/4);
            int q   = t % (BK/4);
            float4 v = *(const float4*)(&Bw[(n0 + row) * K + k0 + q*4]);
            Bs[q*4+0][row] = v.x;
            Bs[q*4+1][row] = v.y;
            Bs[q*4+2][row] = v.z;
            Bs[q*4+3][row] = v.w;
        }
        __syncthreads();

        #pragma unroll
        for (int kk = 0; kk < BK; kk++) {
            float a[TM], b[TN];
            #pragma unroll
            for (int i = 0; i < TM; i++) a[i] = As[kk][ty*TM + i];
            #pragma unroll
            for (int j = 0; j < TN; j++) b[j] = Bs[kk][tx*TN + j];
            #pragma unroll
            for (int i = 0; i < TM; i++)
                #pragma unroll
                for (int j = 0; j < TN; j++)
                    acc[i][j] = fmaf(a[i], b[j], acc[i][j]);
        }
        __syncthreads();
    }

    // epilogue
    #pragma unroll
    for (int i = 0; i < TM; i++) {
        int m = m0 + ty*TM + i;
        #pragma unroll
        for (int j = 0; j < TN; j++) {
            int n = n0 + tx*TN + j;
            float r = acc[i][j];
            if (MODE == MODE_TANH) {
                r = tanhf(r + bias[n]);
            } else if (MODE == MODE_BIAS) {
                r = r + bias[n];
            } else if (MODE == MODE_MULS) {
                float t = tanhT[m * N + n];
                r = r * (1.0f - t * t);
            } else { // MODE_AXPY
                r = base[m * N + n] + scale * r;
            }
            C[m * N + n] = r;
        }
    }
}

extern "C" void kernel_launch(void* const* d_in, const int* in_sizes, int n_in,
                              void* d_out, int out_size)
{
    const float* y  = (const float*)d_in[0];
    const float* W1 = (const float*)d_in[1];
    const float* b1 = (const float*)d_in[2];
    const float* W2 = (const float*)d_in[3];
    const float* b2 = (const float*)d_in[4];
    float* out = (float*)d_out;

    float *pT, *pP, *pV, *pW, *pR, *pR2;
    cudaGetSymbolAddress((void**)&pT,  g_T);
    cudaGetSymbolAddress((void**)&pP,  g_P);
    cudaGetSymbolAddress((void**)&pV,  g_V);
    cudaGetSymbolAddress((void**)&pW,  g_W);
    cudaGetSymbolAddress((void**)&pR,  g_R);
    cudaGetSymbolAddress((void**)&pR2, g_R2);

    // Config L: C is (512 x 1024), K = 256.  64x64 tiles, 256 thr -> 128 blocks
    // Config S: C is (512 x 256),  K = 1024. 32x32 tiles, 128 thr -> 128 blocks
    dim3 gridL(HID/64, BATCH/64);   // (16, 8)
    dim3 gridS(DIM/32, BATCH/32);   // (8, 16)

    const float c6 = 0.01f / 6.0f;
    const float c3 = 0.01f / 3.0f;

    // 1) T = tanh(Y W1^T + b1)                         (512x1024, K=256)
    gemm_nt<64,64,16,4,4,MODE_TANH><<<gridL, 256>>>(
        y, W1, pT, BATCH, HID, DIM, b1, nullptr, nullptr, 0.0f);

    // 2) V = T W2^T + b2                               (512x256, K=1024)
    gemm_nt<32,32,32,2,4,MODE_BIAS><<<gridS, 128>>>(
        pT, W2, pV, BATCH, DIM, HID, b2, nullptr, nullptr, 0.0f);

    // 3) P = (V W1^T) * (1 - T^2)
    gemm_nt<64,64,16,4,4,MODE_MULS><<<gridL, 256>>>(
        pV, W1, pP, BATCH, HID, DIM, nullptr, pT, nullptr, 0.0f);
    // 4) w = V + (0.01/6) * P W2^T
    gemm_nt<32,32,32,2,4,MODE_AXPY><<<gridS, 128>>>(
        pP, W2, pW, BATCH, DIM, HID, nullptr, nullptr, pV, c6);

    // Horner iteration 1: R = w + (A/3) w
    gemm_nt<64,64,16,4,4,MODE_MULS><<<gridL, 256>>>(
        pW, W1, pP, BATCH, HID, DIM, nullptr, pT, nullptr, 0.0f);
    gemm_nt<32,32,32,2,4,MODE_AXPY><<<gridS, 128>>>(
        pP, W2, pR, BATCH, DIM, HID, nullptr, nullptr, pW, c3);

    // Horner iteration 2: R2 = w + (A/3) R
    gemm_nt<64,64,16,4,4,MODE_MULS><<<gridL, 256>>>(
        pR, W1, pP, BATCH, HID, DIM, nullptr, pT, nullptr, 0.0f);
    gemm_nt<32,32,32,2,4,MODE_AXPY><<<gridS, 128>>>(
        pP, W2, pR2, BATCH, DIM, HID, nullptr, nullptr, pW, c3);

    // Horner iteration 3 (final): out = w + (A/3) R2
    gemm_nt<64,64,16,4,4,MODE_MULS><<<gridL, 256>>>(
        pR2, W1, pP, BATCH, HID, DIM, nullptr, pT, nullptr, 0.0f);
    gemm_nt<32,32,32,2,4,MODE_AXPY><<<gridS, 128>>>(
        pP, W2, out, BATCH, DIM, HID, nullptr, nullptr, pW, c3);
}

// round 2
// speedup vs baseline: 1.7796x; 1.7796x over previous
#include <cuda_runtime.h>
#include <math.h>

// EulerRosenbrockModel: B=512, D=256, HID=1024, H_STEP=0.01
// out = (I - A/3)^{-1} (I + A/6) v,  A = 0.01 * W2 diag(1-tanh^2) W1,  v = f(y)
// Matrix-free Neumann series, ||A/3|| <= ~0.015:
//   w = v + (A/6)v ;  out = w + (A/3)(w + (A/3)w)   (truncation err ~3.4e-6)
// 8 GEMM launches total. All GEMMs are NT (both operands K-contiguous).
//
// GEMM kernel: 32x32 output tile, 256 threads = 8 k-split groups of 1 warp.
// Each warp: 8x4 register tile per thread over K/8 slice; smem tree-reduce.

static constexpr int BATCH = 512;
static constexpr int DIM   = 256;
static constexpr int HID   = 1024;

__device__ float g_T[BATCH * HID];   // tanh(W1 y + b1)
__device__ float g_P[BATCH * HID];   // (U W1^T) * (1 - T^2)
__device__ float g_V[BATCH * DIM];   // v = f(y)
__device__ float g_W[BATCH * DIM];   // w = v + (A/6)v
__device__ float g_R[BATCH * DIM];   // Horner iterate

#define MODE_TANH 0
#define MODE_BIAS 1
#define MODE_MULS 2
#define MODE_AXPY 3

// swizzled smem index for a [64][32] k-major tile; 4-word-granular XOR keeps
// float4 fragment loads contiguous & conflict-free, transposing stores <=2-way.
__device__ __forceinline__ int swz(int k, int m) {
    return k * 32 + (m ^ (((k >> 2) & 7) << 2));
}

template<int MODE>
__global__ void __launch_bounds__(256, 2)
gemm32(const float* __restrict__ A, const float* __restrict__ Bw,
       float* __restrict__ C, int K, int N,
       const float* __restrict__ bias, const float* __restrict__ tanhT,
       const float* __restrict__ base, float scale)
{
    __shared__ float arena[4096];          // 16 KB: 2 slabs, reused for reduce
    float* As = arena;                     // [64][32] swizzled (k-major)
    float* Bs = arena + 2048;

    const int tid = threadIdx.x;
    const int g   = tid >> 5;              // k-group 0..7
    const int lt  = tid & 31;
    const int ty  = lt >> 3;               // 0..3  -> 8 m-rows each
    const int tx  = lt & 7;                // 0..7  -> 4 n-cols each
    const int m0  = blockIdx.y * 32;
    const int n0  = blockIdx.x * 32;

    float acc[8][4];
    #pragma unroll
    for (int i = 0; i < 8; i++)
        #pragma unroll
        for (int j = 0; j < 4; j++) acc[i][j] = 0.0f;

    for (int k0 = 0; k0 < K; k0 += 64) {
        __syncthreads();
        // cooperative load of 32x64 slabs of A and B, transposed+swizzled
        #pragma unroll
        for (int t = tid; t < 512; t += 256) {
            const int row = t >> 4;        // 0..31
            const int q   = t & 15;        // 0..15 -> k = 4q..4q+3
            float4 va = *(const float4*)&A [(m0 + row) * K + k0 + q * 4];
            As[swz(q*4+0, row)] = va.x;
            As[swz(q*4+1, row)] = va.y;
            As[swz(q*4+2, row)] = va.z;
            As[swz(q*4+3, row)] = va.w;
            float4 vb = *(const float4*)&Bw[(n0 + row) * K + k0 + q * 4];
            Bs[swz(q*4+0, row)] = vb.x;
            Bs[swz(q*4+1, row)] = vb.y;
            Bs[swz(q*4+2, row)] = vb.z;
            Bs[swz(q*4+3, row)] = vb.w;
        }
        __syncthreads();

        #pragma unroll
        for (int kk = 0; kk < 8; kk++) {
            const int k  = g * 8 + kk;
            const int sa = ((k >> 2) & 7) << 2;
            float a[8], b[4];
            *(float4*)&a[0] = *(const float4*)&As[k * 32 + ((ty * 8    ) ^ sa)];
            *(float4*)&a[4] = *(const float4*)&As[k * 32 + ((ty * 8 + 4) ^ sa)];
            *(float4*)&b[0] = *(const float4*)&Bs[k * 32 + ((tx * 4    ) ^ sa)];
            #pragma unroll
            for (int i = 0; i < 8; i++)
                #pragma unroll
                for (int j = 0; j < 4; j++)
                    acc[i][j] = fmaf(a[i], b[j], acc[i][j]);
        }
    }

    // ---- tree reduce across 8 k-groups (smem arena reused) ----
    float* red = arena;                    // 4 buffers x 1024 floats
    const int lin = (ty * 8) * 32 + tx * 4;

    __syncthreads();
    if (g >= 4) {
        float* dst = red + (g - 4) * 1024 + lin;
        #pragma unroll
        for (int i = 0; i < 8; i++) *(float4*)&dst[i * 32] = *(float4*)&acc[i][0];
    }
    __syncthreads();
    if (g < 4) {
        const float* src = red + g * 1024 + lin;
        #pragma unroll
        for (int i = 0; i < 8; i++) {
            float4 v = *(const float4*)&src[i * 32];
            acc[i][0] += v.x; acc[i][1] += v.y; acc[i][2] += v.z; acc[i][3] += v.w;
        }
    }
    __syncthreads();
    if (g == 2 || g == 3) {
        float* dst = red + (g - 2) * 1024 + lin;
        #pragma unroll
        for (int i = 0; i < 8; i++) *(float4*)&dst[i * 32] = *(float4*)&acc[i][0];
    }
    __syncthreads();
    if (g < 2) {
        const float* src = red + g * 1024 + lin;
        #pragma unroll
        for (int i = 0; i < 8; i++) {
            float4 v = *(const float4*)&src[i * 32];
            acc[i][0] += v.x; acc[i][1] += v.y; acc[i][2] += v.z; acc[i][3] += v.w;
        }
    }
    __syncthreads();
    if (g == 1) {
        float* dst = red + lin;
        #pragma unroll
        for (int i = 0; i < 8; i++) *(float4*)&dst[i * 32] = *(float4*)&acc[i][0];
    }
    __syncthreads();
    if (g == 0) {
        const float* src = red + lin;
        #pragma unroll
        for (int i = 0; i < 8; i++) {
            float4 v = *(const float4*)&src[i * 32];
            acc[i][0] += v.x; acc[i][1] += v.y; acc[i][2] += v.z; acc[i][3] += v.w;
        }
        // epilogue + store (group 0 only: 32 threads write the 32x32 tile)
        #pragma unroll
        for (int i = 0; i < 8; i++) {
            const int m = m0 + ty * 8 + i;
            float4 r;
            float* rp = (float*)&r;
            #pragma unroll
            for (int j = 0; j < 4; j++) {
                const int n = n0 + tx * 4 + j;
                float v = acc[i][j];
                if (MODE == MODE_TANH) {
                    v = tanhf(v + bias[n]);
                } else if (MODE == MODE_BIAS) {
                    v = v + bias[n];
                } else if (MODE == MODE_MULS) {
                    float t = tanhT[m * N + n];
                    v = v * (1.0f - t * t);
                } else { // MODE_AXPY
                    v = base[m * N + n] + scale * v;
                }
                rp[j] = v;
            }
            *(float4*)&C[m * N + n0 + tx * 4] = r;
        }
    }
}

extern "C" void kernel_launch(void* const* d_in, const int* in_sizes, int n_in,
                              void* d_out, int out_size)
{
    const float* y  = (const float*)d_in[0];
    const float* W1 = (const float*)d_in[1];
    const float* b1 = (const float*)d_in[2];
    const float* W2 = (const float*)d_in[3];
    const float* b2 = (const float*)d_in[4];
    float* out = (float*)d_out;

    float *pT, *pP, *pV, *pW, *pR;
    cudaGetSymbolAddress((void**)&pT, g_T);
    cudaGetSymbolAddress((void**)&pP, g_P);
    cudaGetSymbolAddress((void**)&pV, g_V);
    cudaGetSymbolAddress((void**)&pW, g_W);
    cudaGetSymbolAddress((void**)&pR, g_R);

    dim3 gL(HID / 32, BATCH / 32);   // (32, 16) = 512 blocks
    dim3 gS(DIM / 32, BATCH / 32);   // ( 8, 16) = 128 blocks

    const float c6 = 0.01f / 6.0f;
    const float c3 = 0.01f / 3.0f;

    // forward pass: T = tanh(Y W1^T + b1);  V = T W2^T + b2
    gemm32<MODE_TANH><<<gL, 256>>>(y,  W1, pT, DIM, HID, b1, nullptr, nullptr, 0.0f);
    gemm32<MODE_BIAS><<<gS, 256>>>(pT, W2, pV, HID, DIM, b2, nullptr, nullptr, 0.0f);

    // w = V + (h/6) * A~ V   where A~ u = W2 ((W1 u) .* (1-T^2))
    gemm32<MODE_MULS><<<gL, 256>>>(pV, W1, pP, DIM, HID, nullptr, pT, nullptr, 0.0f);
    gemm32<MODE_AXPY><<<gS, 256>>>(pP, W2, pW, HID, DIM, nullptr, nullptr, pV, c6);

    // R = w + (h/3) A~ w
    gemm32<MODE_MULS><<<gL, 256>>>(pW, W1, pP, DIM, HID, nullptr, pT, nullptr, 0.0f);
    gemm32<MODE_AXPY><<<gS, 256>>>(pP, W2, pR, HID, DIM, nullptr, nullptr, pW, c3);

    // out = w + (h/3) A~ R   (Neumann truncation: err ~ ||A/3||^3 ~ 3e-6)
    gemm32<MODE_MULS><<<gL, 256>>>(pR, W1, pP, DIM, HID, nullptr, pT, nullptr, 0.0f);
    gemm32<MODE_AXPY><<<gS, 256>>>(pP, W2, out, HID, DIM, nullptr, nullptr, pW, c3);
}

// round 3
// speedup vs baseline: 2.7379x; 1.5385x over previous
#include <cuda_runtime.h>
#include <math.h>

// EulerRosenbrockModel: B=512, D=256, HID=1024, H_STEP=0.01
// phi(A)v = (I-B)^{-1}(I + B/2) v   with B = (h/3) J,  (A/6 = B/2)
//         = v + 1.5 B v + 1.5 B^2 v + O(B^3)        (||B|| ~ 0.015)
// => out = v + 1.5 * B * (v + B v)    -- only TWO B-applications.
// B u = c3 * W2 ( (W1 u) .* (1 - T^2) ),  c3 = h/3,  T = tanh(W1 y + b1)
//
// GEMMs (all NT, K-contiguous):
//   L-shape: 512x1024, K=256  -> direct, 512 blocks
//   S-shape: 512x256,  K=1024 -> grid split-K (4 chunks of 256, 512 blocks)
//            + elementwise reduce/epilogue kernel (deterministic order)

static constexpr int BATCH = 512;
static constexpr int DIM   = 256;
static constexpr int HID   = 1024;

__device__ float g_T[BATCH * HID];        // tanh(W1 y + b1)
__device__ float g_P[BATCH * HID];        // (U W1^T) .* (1 - T^2)
__device__ float g_V[BATCH * DIM];        // v = f(y)
__device__ float g_U[BATCH * DIM];        // u = v + B v
__device__ float g_part[4 * BATCH * DIM]; // split-K partials

#define MODE_TANH 0
#define MODE_MULS 1
#define MODE_PART 2

// swizzled smem index for a [64][32] k-major tile
__device__ __forceinline__ int swz(int k, int m) {
    return k * 32 + (m ^ (((k >> 2) & 7) << 2));
}

// 32x32 output tile, K=256 per block (grid.z selects the K chunk).
// 256 threads = 8 k-split warps; 8x4 regs/thread; smem tree reduce.
template<int MODE>
__global__ void __launch_bounds__(256, 2)
gemm32(const float* __restrict__ A, int lda,
       const float* __restrict__ Bw, int ldb,
       float* __restrict__ C, int N,
       const float* __restrict__ bias, const float* __restrict__ tanhT)
{
    __shared__ float arena[4096];
    float* As = arena;
    float* Bs = arena + 2048;

    const int tid = threadIdx.x;
    const int g   = tid >> 5;
    const int lt  = tid & 31;
    const int ty  = lt >> 3;
    const int tx  = lt & 7;
    const int m0  = blockIdx.y * 32;
    const int n0  = blockIdx.x * 32;
    const int z   = blockIdx.z;

    const float* Ab = A  + z * 256;   // K-chunk offset
    const float* Bb = Bw + z * 256;

    float acc[8][4];
    #pragma unroll
    for (int i = 0; i < 8; i++)
        #pragma unroll
        for (int j = 0; j < 4; j++) acc[i][j] = 0.0f;

    #pragma unroll
    for (int k0 = 0; k0 < 256; k0 += 64) {
        __syncthreads();
        #pragma unroll
        for (int t = tid; t < 512; t += 256) {
            const int row = t >> 4;
            const int q   = t & 15;
            float4 va = *(const float4*)&Ab[(m0 + row) * lda + k0 + q * 4];
            As[swz(q*4+0, row)] = va.x;
            As[swz(q*4+1, row)] = va.y;
            As[swz(q*4+2, row)] = va.z;
            As[swz(q*4+3, row)] = va.w;
            float4 vb = *(const float4*)&Bb[(n0 + row) * ldb + k0 + q * 4];
            Bs[swz(q*4+0, row)] = vb.x;
            Bs[swz(q*4+1, row)] = vb.y;
            Bs[swz(q*4+2, row)] = vb.z;
            Bs[swz(q*4+3, row)] = vb.w;
        }
        __syncthreads();

        #pragma unroll
        for (int kk = 0; kk < 8; kk++) {
            const int k  = g * 8 + kk;
            const int sa = ((k >> 2) & 7) << 2;
            float a[8], b[4];
            *(float4*)&a[0] = *(const float4*)&As[k * 32 + ((ty * 8    ) ^ sa)];
            *(float4*)&a[4] = *(const float4*)&As[k * 32 + ((ty * 8 + 4) ^ sa)];
            *(float4*)&b[0] = *(const float4*)&Bs[k * 32 + ((tx * 4    ) ^ sa)];
            #pragma unroll
            for (int i = 0; i < 8; i++)
                #pragma unroll
                for (int j = 0; j < 4; j++)
                    acc[i][j] = fmaf(a[i], b[j], acc[i][j]);
        }
    }

    // tree reduce across 8 k-groups
    float* red = arena;
    const int lin = (ty * 8) * 32 + tx * 4;

    __syncthreads();
    if (g >= 4) {
        float* dst = red + (g - 4) * 1024 + lin;
        #pragma unroll
        for (int i = 0; i < 8; i++) *(float4*)&dst[i * 32] = *(float4*)&acc[i][0];
    }
    __syncthreads();
    if (g < 4) {
        const float* src = red + g * 1024 + lin;
        #pragma unroll
        for (int i = 0; i < 8; i++) {
            float4 v = *(const float4*)&src[i * 32];
            acc[i][0] += v.x; acc[i][1] += v.y; acc[i][2] += v.z; acc[i][3] += v.w;
        }
    }
    __syncthreads();
    if (g == 2 || g == 3) {
        float* dst = red + (g - 2) * 1024 + lin;
        #pragma unroll
        for (int i = 0; i < 8; i++) *(float4*)&dst[i * 32] = *(float4*)&acc[i][0];
    }
    __syncthreads();
    if (g < 2) {
        const float* src = red + g * 1024 + lin;
        #pragma unroll
        for (int i = 0; i < 8; i++) {
            float4 v = *(const float4*)&src[i * 32];
            acc[i][0] += v.x; acc[i][1] += v.y; acc[i][2] += v.z; acc[i][3] += v.w;
        }
    }
    __syncthreads();
    if (g == 1) {
        float* dst = red + lin;
        #pragma unroll
        for (int i = 0; i < 8; i++) *(float4*)&dst[i * 32] = *(float4*)&acc[i][0];
    }
    __syncthreads();
    if (g == 0) {
        const float* src = red + lin;
        #pragma unroll
        for (int i = 0; i < 8; i++) {
            float4 v = *(const float4*)&src[i * 32];
            acc[i][0] += v.x; acc[i][1] += v.y; acc[i][2] += v.z; acc[i][3] += v.w;
        }
        float* Cb = (MODE == MODE_PART) ? (C + z * (BATCH * DIM)) : C;
        #pragma unroll
        for (int i = 0; i < 8; i++) {
            const int m = m0 + ty * 8 + i;
            float4 r;
            float* rp = (float*)&r;
            #pragma unroll
            for (int j = 0; j < 4; j++) {
                const int n = n0 + tx * 4 + j;
                float v = acc[i][j];
                if (MODE == MODE_TANH) {
                    v = tanhf(v + bias[n]);
                } else if (MODE == MODE_MULS) {
                    float t = tanhT[m * N + n];
                    v = v * (1.0f - t * t);
                }
                rp[j] = v;
            }
            *(float4*)&Cb[m * N + n0 + tx * 4] = r;
        }
    }
}

#define RED_BIAS 0
#define RED_AXPY 1

// out = epilogue( part0+part1+part2+part3 ); 131072 elems, float4 per thread
template<int RMODE>
__global__ void __launch_bounds__(256)
reduce_ep(const float* __restrict__ part, const float* __restrict__ aux,
          float scale, float* __restrict__ out)
{
    const int e4 = (blockIdx.x * 256 + threadIdx.x) * 4;
    float4 s0 = *(const float4*)&part[e4];
    float4 s1 = *(const float4*)&part[BATCH*DIM     + e4];
    float4 s2 = *(const float4*)&part[BATCH*DIM * 2 + e4];
    float4 s3 = *(const float4*)&part[BATCH*DIM * 3 + e4];
    float4 s;
    s.x = (s0.x + s1.x) + (s2.x + s3.x);
    s.y = (s0.y + s1.y) + (s2.y + s3.y);
    s.z = (s0.z + s1.z) + (s2.z + s3.z);
    s.w = (s0.w + s1.w) + (s2.w + s3.w);
    float4 r;
    if (RMODE == RED_BIAS) {
        float4 b = *(const float4*)&aux[e4 & (DIM - 1)];   // b2[n], n = e4 % 256
        r.x = s.x + b.x; r.y = s.y + b.y; r.z = s.z + b.z; r.w = s.w + b.w;
    } else {
        float4 b = *(const float4*)&aux[e4];               // base (= v)
        r.x = fmaf(scale, s.x, b.x); r.y = fmaf(scale, s.y, b.y);
        r.z = fmaf(scale, s.z, b.z); r.w = fmaf(scale, s.w, b.w);
    }
    *(float4*)&out[e4] = r;
}

extern "C" void kernel_launch(void* const* d_in, const int* in_sizes, int n_in,
                              void* d_out, int out_size)
{
    const float* y  = (const float*)d_in[0];
    const float* W1 = (const float*)d_in[1];
    const float* b1 = (const float*)d_in[2];
    const float* W2 = (const float*)d_in[3];
    const float* b2 = (const float*)d_in[4];
    float* out = (float*)d_out;

    float *pT, *pP, *pV, *pU, *pPart;
    cudaGetSymbolAddress((void**)&pT, g_T);
    cudaGetSymbolAddress((void**)&pP, g_P);
    cudaGetSymbolAddress((void**)&pV, g_V);
    cudaGetSymbolAddress((void**)&pU, g_U);
    cudaGetSymbolAddress((void**)&pPart, g_part);

    dim3 gL(HID / 32, BATCH / 32, 1);   // (32,16,1) = 512 blocks
    dim3 gS(DIM / 32, BATCH / 32, 4);   // ( 8,16,4) = 512 blocks
    const int gR = (BATCH * DIM) / (256 * 4);  // 128 blocks

    const float c3 = 0.01f / 3.0f;

    // forward: T = tanh(Y W1^T + b1);  V = T W2^T + b2
    gemm32<MODE_TANH><<<gL, 256>>>(y, DIM, W1, DIM, pT, HID, b1, nullptr);
    gemm32<MODE_PART><<<gS, 256>>>(pT, HID, W2, HID, pPart, DIM, nullptr, nullptr);
    reduce_ep<RED_BIAS><<<gR, 256>>>(pPart, b2, 0.0f, pV);

    // u = v + B v
    gemm32<MODE_MULS><<<gL, 256>>>(pV, DIM, W1, DIM, pP, HID, nullptr, pT);
    gemm32<MODE_PART><<<gS, 256>>>(pP, HID, W2, HID, pPart, DIM, nullptr, nullptr);
    reduce_ep<RED_AXPY><<<gR, 256>>>(pPart, pV, c3, pU);

    // out = v + 1.5 B u    (phi ~ I + 1.5B + 1.5B^2; err ~ 1.5||B||^3 ~ 5e-6)
    gemm32<MODE_MULS><<<gL, 256>>>(pU, DIM, W1, DIM, pP, HID, nullptr, pT);
    gemm32<MODE_PART><<<gS, 256>>>(pP, HID, W2, HID, pPart, DIM, nullptr, nullptr);
    reduce_ep<RED_AXPY><<<gR, 256>>>(pPart, pV, 1.5f * c3, out);
}

// round 5
// speedup vs baseline: 3.8396x; 1.4024x over previous
#include <cuda_runtime.h>
#include <cuda_bf16.h>
#include <cstdint>
#include <math.h>

// EulerRosenbrockModel: B=512, D=256, HID=1024, H_STEP=0.01
// phi(A)v = v + 1.5 B v + 1.5 B^2 v,  B = (h/3) J  (||B|| ~ 0.015)
// GEMMs on the tensor pipe via mma.sync bf16 (sm_80 PTX -> valid on compute_103)
// fp32 precision via bf16 double-split, 3 regions: hi*hi + hi*lo + lo*hi.
// Split-bf16 operands precomputed in global: [row][ hi(0..K-1) | lo(K..2K-1) ].

static constexpr int BATCH = 512;
static constexpr int DIM   = 256;
static constexpr int HID   = 1024;

// fp32 scratch
__device__ float g_T   [BATCH * HID];        // tanh(W1 y + b1)  (for 1-T^2)
__device__ float g_V   [BATCH * DIM];        // v = f(y)
__device__ float g_part[4 * BATCH * DIM];    // split-K partials
// split-bf16 operands
__device__ __nv_bfloat16 g_ys [BATCH * 2 * DIM];   // y split
__device__ __nv_bfloat16 g_W1s[HID   * 2 * DIM];   // W1 split
__device__ __nv_bfloat16 g_W2s[DIM   * 2 * HID];   // W2 split
__device__ __nv_bfloat16 g_Ts [BATCH * 2 * HID];   // T split
__device__ __nv_bfloat16 g_Ps [BATCH * 2 * HID];   // P split
__device__ __nv_bfloat16 g_Vs [BATCH * 2 * DIM];   // V split
__device__ __nv_bfloat16 g_Us [BATCH * 2 * DIM];   // U split

// ---------------- low-level helpers ----------------
__device__ __forceinline__ uint32_t smem_u32(const void* p) {
    uint32_t a;
    asm("{ .reg .u64 t; cvta.to.shared.u64 t, %1; cvt.u32.u64 %0, t; }"
        : "=r"(a) : "l"(p));
    return a;
}
__device__ __forceinline__ void cp16(uint32_t dst, const void* src) {
    asm volatile("cp.async.cg.shared.global [%0], [%1], 16;" :: "r"(dst), "l"(src));
}
__device__ __forceinline__ void cp_commit() {
    asm volatile("cp.async.commit_group;" ::: "memory");
}
template<int N>
__device__ __forceinline__ void cp_wait() {
    asm volatile("cp.async.wait_group %0;" :: "n"(N) : "memory");
}
__device__ __forceinline__ void ldm4(uint32_t* r, uint32_t addr) {
    asm volatile("ldmatrix.sync.aligned.m8n8.x4.shared.b16 {%0,%1,%2,%3}, [%4];"
        : "=r"(r[0]), "=r"(r[1]), "=r"(r[2]), "=r"(r[3]) : "r"(addr));
}
__device__ __forceinline__ void mma_bf16(float* d, const uint32_t* a, const uint32_t* b) {
    asm volatile("mma.sync.aligned.m16n8k16.row.col.f32.bf16.bf16.f32 "
        "{%0,%1,%2,%3}, {%4,%5,%6,%7}, {%8,%9}, {%0,%1,%2,%3};"
        : "+f"(d[0]), "+f"(d[1]), "+f"(d[2]), "+f"(d[3])
        : "r"(a[0]), "r"(a[1]), "r"(a[2]), "r"(a[3]), "r"(b[0]), "r"(b[1]));
}
// store fp32 pair (v0,v1) as hi/lo bf16 split at Cs[m][n] (layout [m][hi K | lo K])
__device__ __forceinline__ void st_split(__nv_bfloat16* Cs, int Kw, int m, int n,
                                         float v0, float v1) {
    __nv_bfloat162 h = __floats2bfloat162_rn(v0, v1);
    float l0 = v0 - __bfloat162float(h.x);
    float l1 = v1 - __bfloat162float(h.y);
    __nv_bfloat162 l = __floats2bfloat162_rn(l0, l1);
    *(__nv_bfloat162*)&Cs[(size_t)m * (2 * Kw) + n]      = h;
    *(__nv_bfloat162*)&Cs[(size_t)m * (2 * Kw) + Kw + n] = l;
}

#define MODE_TANH 0   // C fp32 = tanh(acc + bias[n]); Cs split
#define MODE_MULS 1   // Cs split = acc * (1 - T^2)
#define MODE_PART 2   // C fp32 partial (z-offset)

// C[M,N] (CTA tile 64x64) = A[M,Kf32] * B[N,Kf32]^T via split-bf16 (K_eff = 3*Kf32)
// A, B: bf16 split panels [rows][2*Ka], z selects 256-wide f32-K chunk.
template<int MODE>
__global__ void __launch_bounds__(256)
mmagemm(const __nv_bfloat16* __restrict__ A, const __nv_bfloat16* __restrict__ Bw,
        int Ka, float* __restrict__ C, __nv_bfloat16* __restrict__ Cs,
        int Nglob, const float* __restrict__ bias, const float* __restrict__ tanhT)
{
    __shared__ __align__(1024) char smem[32768];  // A0,B0,A1,B1: 8KB each
    const uint32_t sb = smem_u32(smem);
    const uint32_t sA[2] = {sb, sb + 16384};
    const uint32_t sB[2] = {sb + 8192, sb + 24576};

    const int tid = threadIdx.x;
    const int wid = tid >> 5;
    const int lid = tid & 31;
    const int wm  = wid >> 2;          // 0..1  (m: 32 rows)
    const int wn  = wid & 3;           // 0..3  (n: 16 cols)
    const int m0  = blockIdx.y * 64;
    const int n0  = blockIdx.x * 64;
    const int zoff = blockIdx.z * 256;
    const int lda = 2 * Ka;

    float acc[2][2][4];
    #pragma unroll
    for (int f = 0; f < 2; f++)
        #pragma unroll
        for (int g = 0; g < 2; g++)
            #pragma unroll
            for (int q = 0; q < 4; q++) acc[f][g][q] = 0.0f;

    // fragment address components (per-thread constants)
    const int m_l = wm * 32 + ((lid >> 3) & 1) * 8 + (lid & 7);
    const int n_l = wn * 16 + (lid >> 4) * 8 + (lid & 7);
    const int a_so = (lid >> 4);          // seg offset for A (0/1)
    const int b_so = ((lid >> 3) & 1);    // seg offset for B (0/1)
    const uint32_t ax = (uint32_t)((m_l & 7) << 4);  // swizzle XOR const
    const uint32_t bx = (uint32_t)((n_l & 7) << 4);

    // issue cp.async for chunk cc into buffer cc&1
    auto issue = [&](int cc) {
        const int r  = cc >> 2;                 // 0 hi*hi, 1 hi*lo, 2 lo*hi
        const int kb = (cc & 3) * 64;
        const int ak = zoff + kb + (r == 2 ? Ka : 0);
        const int bk = zoff + kb + (r == 1 ? Ka : 0);
        const uint32_t ab = sA[cc & 1], bb = sB[cc & 1];
        #pragma unroll
        for (int t = tid; t < 512; t += 256) {
            const int row = t >> 3, seg = t & 7;
            const uint32_t sw = (uint32_t)(seg * 16) ^ (uint32_t)((row & 7) << 4);
            cp16(ab + row * 128 + sw, A  + (size_t)(m0 + row) * lda + ak + seg * 8);
            cp16(bb + row * 128 + sw, Bw + (size_t)(n0 + row) * lda + bk + seg * 8);
        }
    };

    issue(0);
    cp_commit();

    #pragma unroll 1
    for (int c = 0; c < 12; c++) {
        if (c + 1 < 12) { issue(c + 1); cp_commit(); cp_wait<1>(); }
        else            { cp_wait<0>(); }
        __syncthreads();

        const uint32_t ab = sA[c & 1], bb = sB[c & 1];
        const uint32_t aRow = ab + m_l * 128;
        const uint32_t bRow = bb + n_l * 128;
        #pragma unroll
        for (int k = 0; k < 4; k++) {
            uint32_t a0[4], a1[4], b[4];
            const uint32_t as = (uint32_t)((k * 2 + a_so) * 16) ^ ax;
            const uint32_t bs = (uint32_t)((k * 2 + b_so) * 16) ^ bx;
            ldm4(a0, aRow + as);
            ldm4(a1, aRow + 2048 + as);          // +16 rows * 128B
            ldm4(b,  bRow + bs);
            mma_bf16(acc[0][0], a0, b);
            mma_bf16(acc[0][1], a0, b + 2);
            mma_bf16(acc[1][0], a1, b);
            mma_bf16(acc[1][1], a1, b + 2);
        }
        __syncthreads();
    }

    // ---- epilogue ----
    const int gid  = lid >> 2;
    const int tid4 = lid & 3;
    #pragma unroll
    for (int f = 0; f < 2; f++) {
        #pragma unroll
        for (int g = 0; g < 2; g++) {
            const int m = m0 + wm * 32 + f * 16 + gid;
            const int n = n0 + wn * 16 + g * 8 + tid4 * 2;
            const float* ac = acc[f][g];
            if (MODE == MODE_TANH) {
                const float b0v = bias[n], b1v = bias[n + 1];
                float v00 = tanhf(ac[0] + b0v), v01 = tanhf(ac[1] + b1v);
                float v10 = tanhf(ac[2] + b0v), v11 = tanhf(ac[3] + b1v);
                *(float2*)&C[(size_t)m * Nglob + n]       = make_float2(v00, v01);
                *(float2*)&C[(size_t)(m + 8) * Nglob + n] = make_float2(v10, v11);
                st_split(Cs, Nglob, m,     n, v00, v01);
                st_split(Cs, Nglob, m + 8, n, v10, v11);
            } else if (MODE == MODE_MULS) {
                float2 t0 = *(const float2*)&tanhT[(size_t)m * Nglob + n];
                float2 t1 = *(const float2*)&tanhT[(size_t)(m + 8) * Nglob + n];
                st_split(Cs, Nglob, m,     n, ac[0] * (1.0f - t0.x * t0.x),
                                              ac[1] * (1.0f - t0.y * t0.y));
                st_split(Cs, Nglob, m + 8, n, ac[2] * (1.0f - t1.x * t1.x),
                                              ac[3] * (1.0f - t1.y * t1.y));
            } else {  // MODE_PART
                float* Cb = C + (size_t)blockIdx.z * (BATCH * DIM);
                *(float2*)&Cb[(size_t)m * Nglob + n]       = make_float2(ac[0], ac[1]);
                *(float2*)&Cb[(size_t)(m + 8) * Nglob + n] = make_float2(ac[2], ac[3]);
            }
        }
    }
}

// fp32 [R][K] -> split bf16 [R][2K]
__global__ void __launch_bounds__(256)
split_k(const float* __restrict__ in, __nv_bfloat16* __restrict__ outs, int K)
{
    const int e4 = (blockIdx.x * 256 + threadIdx.x) * 4;
    const int row = e4 / K, k = e4 % K;
    float4 v = *(const float4*)&in[e4];
    __nv_bfloat162 h0 = __floats2bfloat162_rn(v.x, v.y);
    __nv_bfloat162 h1 = __floats2bfloat162_rn(v.z, v.w);
    __nv_bfloat162 l0 = __floats2bfloat162_rn(v.x - __bfloat162float(h0.x),
                                              v.y - __bfloat162float(h0.y));
    __nv_bfloat162 l1 = __floats2bfloat162_rn(v.z - __bfloat162float(h1.x),
                                              v.w - __bfloat162float(h1.y));
    *(__nv_bfloat162*)&outs[(size_t)row * 2 * K + k]         = h0;
    *(__nv_bfloat162*)&outs[(size_t)row * 2 * K + k + 2]     = h1;
    *(__nv_bfloat162*)&outs[(size_t)row * 2 * K + K + k]     = l0;
    *(__nv_bfloat162*)&outs[(size_t)row * 2 * K + K + k + 2] = l1;
}

// RMODE 0: out = sum + bias (fp32 + split);  1: split(aux + scale*sum) only;
//       2: out = aux + scale*sum (fp32 only)
template<int RMODE>
__global__ void __launch_bounds__(256)
reduce_ep(const float* __restrict__ part, const float* __restrict__ aux,
          float scale, float* __restrict__ out, __nv_bfloat16* __restrict__ outs)
{
    const int e4 = (blockIdx.x * 256 + threadIdx.x) * 4;
    float4 s0 = *(const float4*)&part[e4];
    float4 s1 = *(const float4*)&part[BATCH * DIM     + e4];
    float4 s2 = *(const float4*)&part[BATCH * DIM * 2 + e4];
    float4 s3 = *(const float4*)&part[BATCH * DIM * 3 + e4];
    float4 r;
    r.x = (s0.x + s1.x) + (s2.x + s3.x);
    r.y = (s0.y + s1.y) + (s2.y + s3.y);
    r.z = (s0.z + s1.z) + (s2.z + s3.z);
    r.w = (s0.w + s1.w) + (s2.w + s3.w);
    if (RMODE == 0) {
        float4 b = *(const float4*)&aux[e4 & (DIM - 1)];
        r.x += b.x; r.y += b.y; r.z += b.z; r.w += b.w;
    } else {
        float4 b = *(const float4*)&aux[e4];
        r.x = fmaf(scale, r.x, b.x); r.y = fmaf(scale, r.y, b.y);
        r.z = fmaf(scale, r.z, b.z); r.w = fmaf(scale, r.w, b.w);
    }
    if (RMODE == 0 || RMODE == 2)
        *(float4*)&out[e4] = r;
    if (RMODE <= 1) {
        const int row = e4 >> 8, k = e4 & 255;
        __nv_bfloat162 h0 = __floats2bfloat162_rn(r.x, r.y);
        __nv_bfloat162 h1 = __floats2bfloat162_rn(r.z, r.w);
        __nv_bfloat162 l0 = __floats2bfloat162_rn(r.x - __bfloat162float(h0.x),
                                                  r.y - __bfloat162float(h0.y));
        __nv_bfloat162 l1 = __floats2bfloat162_rn(r.z - __bfloat162float(h1.x),
                                                  r.w - __bfloat162float(h1.y));
        *(__nv_bfloat162*)&outs[(size_t)row * 512 + k]           = h0;
        *(__nv_bfloat162*)&outs[(size_t)row * 512 + k + 2]       = h1;
        *(__nv_bfloat162*)&outs[(size_t)row * 512 + 256 + k]     = l0;
        *(__nv_bfloat162*)&outs[(size_t)row * 512 + 256 + k + 2] = l1;
    }
}

extern "C" void kernel_launch(void* const* d_in, const int* in_sizes, int n_in,
                              void* d_out, int out_size)
{
    const float* y  = (const float*)d_in[0];
    const float* W1 = (const float*)d_in[1];
    const float* b1 = (const float*)d_in[2];
    const float* W2 = (const float*)d_in[3];
    const float* b2 = (const float*)d_in[4];
    float* out = (float*)d_out;

    float *pT, *pV, *pPart;
    __nv_bfloat16 *pYs, *pW1s, *pW2s, *pTs, *pPs, *pVs, *pUs;
    cudaGetSymbolAddress((void**)&pT,    g_T);
    cudaGetSymbolAddress((void**)&pV,    g_V);
    cudaGetSymbolAddress((void**)&pPart, g_part);
    cudaGetSymbolAddress((void**)&pYs,   g_ys);
    cudaGetSymbolAddress((void**)&pW1s,  g_W1s);
    cudaGetSymbolAddress((void**)&pW2s,  g_W2s);
    cudaGetSymbolAddress((void**)&pTs,   g_Ts);
    cudaGetSymbolAddress((void**)&pPs,   g_Ps);
    cudaGetSymbolAddress((void**)&pVs,   g_Vs);
    cudaGetSymbolAddress((void**)&pUs,   g_Us);

    dim3 gL(HID / 64, BATCH / 64, 1);   // (16, 8, 1) = 128 CTAs
    dim3 gS(DIM / 64, BATCH / 64, 4);   // ( 4, 8, 4) = 128 CTAs
    const int gR = (BATCH * DIM) / (256 * 4);  // 128

    const float c3 = 0.01f / 3.0f;

    // operand splits
    split_k<<<(BATCH * DIM) / 1024, 256>>>(y,  pYs,  DIM);
    split_k<<<(HID * DIM)   / 1024, 256>>>(W1, pW1s, DIM);
    split_k<<<(DIM * HID)   / 1024, 256>>>(W2, pW2s, HID);

    // T = tanh(y W1^T + b1);  V = T W2^T + b2
    mmagemm<MODE_TANH><<<gL, 256>>>(pYs, pW1s, DIM, pT, pTs, HID, b1, nullptr);
    mmagemm<MODE_PART><<<gS, 256>>>(pTs, pW2s, HID, pPart, nullptr, DIM, nullptr, nullptr);
    reduce_ep<0><<<gR, 256>>>(pPart, b2, 0.0f, pV, pVs);

    // u = v + B v
    mmagemm<MODE_MULS><<<gL, 256>>>(pVs, pW1s, DIM, nullptr, pPs, HID, nullptr, pT);
    mmagemm<MODE_PART><<<gS, 256>>>(pPs, pW2s, HID, pPart, nullptr, DIM, nullptr, nullptr);
    reduce_ep<1><<<gR, 256>>>(pPart, pV, c3, nullptr, pUs);

    // out = v + 1.5 B u
    mmagemm<MODE_MULS><<<gL, 256>>>(pUs, pW1s, DIM, nullptr, pPs, HID, nullptr, pT);
    mmagemm<MODE_PART><<<gS, 256>>>(pPs, pW2s, HID, pPart, nullptr, DIM, nullptr, nullptr);
    reduce_ep<2><<<gR, 256>>>(pPart, pV, 1.5f * c3, out, nullptr);
}

// round 7
// speedup vs baseline: 5.4250x; 1.4129x over previous
#include <cuda_runtime.h>
#include <cuda_bf16.h>
#include <cstdint>
#include <math.h>

// EulerRosenbrockModel: B=512, D=256, HID=1024, H_STEP=0.01
// phi(A)v = v + 1.5 B v + 1.5 B^2 v,  B = (h/3) J  (||B|| ~ 0.015)
// Tensor-pipe GEMMs via mma.sync bf16 (sm_80 PTX, valid on compute_103).
// Forward pass (T, V): bf16 double-split, 3 regions (hi*hi + hi*lo + lo*hi).
// Correction path (B v, B^2 v): plain bf16 (corrections are ~2% of output;
//   0.2% bf16 error on them -> ~4e-5 relative on output).

static constexpr int BATCH = 512;
static constexpr int DIM   = 256;
static constexpr int HID   = 1024;

// fp32 scratch
__device__ float g_T   [BATCH * HID];
__device__ float g_V   [BATCH * DIM];
__device__ float g_part[4 * BATCH * DIM];
// split bf16 panels [row][ hi(K) | lo(K) ]
__device__ __nv_bfloat16 g_ys [BATCH * 2 * DIM];
__device__ __nv_bfloat16 g_W1s[HID   * 2 * DIM];
__device__ __nv_bfloat16 g_W2s[DIM   * 2 * HID];
__device__ __nv_bfloat16 g_Ts [BATCH * 2 * HID];
// plain bf16 panels
__device__ __nv_bfloat16 g_Pp [BATCH * HID];
__device__ __nv_bfloat16 g_Vp [BATCH * DIM];
__device__ __nv_bfloat16 g_Up [BATCH * DIM];

// ---------------- low-level helpers ----------------
__device__ __forceinline__ uint32_t smem_u32(const void* p) {
    uint32_t a;
    asm("{ .reg .u64 t; cvta.to.shared.u64 t, %1; cvt.u32.u64 %0, t; }"
        : "=r"(a) : "l"(p));
    return a;
}
__device__ __forceinline__ void cp16(uint32_t dst, const void* src) {
    asm volatile("cp.async.cg.shared.global [%0], [%1], 16;" :: "r"(dst), "l"(src));
}
__device__ __forceinline__ void cp_commit() {
    asm volatile("cp.async.commit_group;" ::: "memory");
}
template<int N>
__device__ __forceinline__ void cp_wait() {
    asm volatile("cp.async.wait_group %0;" :: "n"(N) : "memory");
}
__device__ __forceinline__ void ldm4(uint32_t* r, uint32_t addr) {
    asm volatile("ldmatrix.sync.aligned.m8n8.x4.shared.b16 {%0,%1,%2,%3}, [%4];"
        : "=r"(r[0]), "=r"(r[1]), "=r"(r[2]), "=r"(r[3]) : "r"(addr));
}
__device__ __forceinline__ void mma_bf16(float* d, const uint32_t* a, const uint32_t* b) {
    asm volatile("mma.sync.aligned.m16n8k16.row.col.f32.bf16.bf16.f32 "
        "{%0,%1,%2,%3}, {%4,%5,%6,%7}, {%8,%9}, {%0,%1,%2,%3};"
        : "+f"(d[0]), "+f"(d[1]), "+f"(d[2]), "+f"(d[3])
        : "r"(a[0]), "r"(a[1]), "r"(a[2]), "r"(a[3]), "r"(b[0]), "r"(b[1]));
}
__device__ __forceinline__ void st_split(__nv_bfloat16* Cs, int Kw, int m, int n,
                                         float v0, float v1) {
    __nv_bfloat162 h = __floats2bfloat162_rn(v0, v1);
    float l0 = v0 - __bfloat162float(h.x);
    float l1 = v1 - __bfloat162float(h.y);
    __nv_bfloat162 l = __floats2bfloat162_rn(l0, l1);
    *(__nv_bfloat162*)&Cs[(size_t)m * (2 * Kw) + n]      = h;
    *(__nv_bfloat162*)&Cs[(size_t)m * (2 * Kw) + Kw + n] = l;
}

#define MODE_TANH 0   // C fp32 = tanh(acc+bias); Cs = split(result)
#define MODE_MULS 1   // Cs plain bf16 = acc * (1 - T^2)
#define MODE_PART 2   // C fp32 partial at z offset

// CTA tile 64x64; A,B bf16 panels (row stride lda/ldb elements).
// NREG=3: K chunks cover regions hi*hi, hi*lo, lo*hi (Ka = f32 K width).
// NREG=1: plain bf16, 4 chunks. Per-CTA f32-K is always 256 (z selects chunk).
// 3-stage cp.async ring, one __syncthreads per chunk.
template<int MODE, int NREG>
__global__ void __launch_bounds__(256)
mmagemm(const __nv_bfloat16* __restrict__ A, int lda,
        const __nv_bfloat16* __restrict__ Bw, int ldb, int Ka,
        float* __restrict__ C, __nv_bfloat16* __restrict__ Cs,
        int Nglob, const float* __restrict__ bias, const float* __restrict__ tanhT)
{
    constexpr int CHUNKS = 4 * NREG;
    __shared__ __align__(1024) char smem[49152];   // 3 stages x (8KB A + 8KB B)
    const uint32_t sb = smem_u32(smem);

    const int tid = threadIdx.x;
    const int wid = tid >> 5;
    const int lid = tid & 31;
    const int wm  = wid >> 2;
    const int wn  = wid & 3;
    const int m0  = blockIdx.y * 64;
    const int n0  = blockIdx.x * 64;
    const int zoff = blockIdx.z * 256;

    float acc[2][2][4];
    #pragma unroll
    for (int f = 0; f < 2; f++)
        #pragma unroll
        for (int g = 0; g < 2; g++)
            #pragma unroll
            for (int q = 0; q < 4; q++) acc[f][g][q] = 0.0f;

    const int m_l = wm * 32 + ((lid >> 3) & 1) * 8 + (lid & 7);
    const int n_l = wn * 16 + (lid >> 4) * 8 + (lid & 7);
    const int a_so = (lid >> 4);
    const int b_so = ((lid >> 3) & 1);
    const uint32_t ax = (uint32_t)((m_l & 7) << 4);
    const uint32_t bx = (uint32_t)((n_l & 7) << 4);

    auto issue = [&](int cc, int st) {
        const int r  = (NREG == 3) ? (cc >> 2) : 0;
        const int kb = (cc & 3) * 64;
        const int ak = zoff + kb + (r == 2 ? Ka : 0);
        const int bk = zoff + kb + (r == 1 ? Ka : 0);
        const uint32_t ab = sb + st * 16384;
        const uint32_t bb = ab + 8192;
        #pragma unroll
        for (int t = tid; t < 512; t += 256) {
            const int row = t >> 3, seg = t & 7;
            const uint32_t sw = (uint32_t)(seg * 16) ^ (uint32_t)((row & 7) << 4);
            cp16(ab + row * 128 + sw, A  + (size_t)(m0 + row) * lda + ak + seg * 8);
            cp16(bb + row * 128 + sw, Bw + (size_t)(n0 + row) * ldb + bk + seg * 8);
        }
    };

    // prologue: stages 0,1
    issue(0, 0); cp_commit();
    issue(1, 1); cp_commit();

    int rst = 0, wst = 2;
    #pragma unroll 1
    for (int c = 0; c < CHUNKS; c++) {
        if (c + 1 < CHUNKS) cp_wait<1>(); else cp_wait<0>();
        __syncthreads();
        if (c + 2 < CHUNKS) { issue(c + 2, wst); cp_commit(); }

        const uint32_t ab = sb + rst * 16384;
        const uint32_t aRow = ab + m_l * 128;
        const uint32_t bRow = ab + 8192 + n_l * 128;
        #pragma unroll
        for (int k = 0; k < 4; k++) {
            uint32_t a0[4], a1[4], b[4];
            const uint32_t as = (uint32_t)((k * 2 + a_so) * 16) ^ ax;
            const uint32_t bs = (uint32_t)((k * 2 + b_so) * 16) ^ bx;
            ldm4(a0, aRow + as);
            ldm4(a1, aRow + 2048 + as);
            ldm4(b,  bRow + bs);
            mma_bf16(acc[0][0], a0, b);
            mma_bf16(acc[0][1], a0, b + 2);
            mma_bf16(acc[1][0], a1, b);
            mma_bf16(acc[1][1], a1, b + 2);
        }
        rst = (rst == 2) ? 0 : rst + 1;
        wst = (wst == 2) ? 0 : wst + 1;
    }

    // ---- epilogue ----
    const int gid  = lid >> 2;
    const int tid4 = lid & 3;
    #pragma unroll
    for (int f = 0; f < 2; f++) {
        #pragma unroll
        for (int g = 0; g < 2; g++) {
            const int m = m0 + wm * 32 + f * 16 + gid;
            const int n = n0 + wn * 16 + g * 8 + tid4 * 2;
            const float* ac = acc[f][g];
            if (MODE == MODE_TANH) {
                const float b0v = bias[n], b1v = bias[n + 1];
                float v00 = tanhf(ac[0] + b0v), v01 = tanhf(ac[1] + b1v);
                float v10 = tanhf(ac[2] + b0v), v11 = tanhf(ac[3] + b1v);
                *(float2*)&C[(size_t)m * Nglob + n]       = make_float2(v00, v01);
                *(float2*)&C[(size_t)(m + 8) * Nglob + n] = make_float2(v10, v11);
                st_split(Cs, Nglob, m,     n, v00, v01);
                st_split(Cs, Nglob, m + 8, n, v10, v11);
            } else if (MODE == MODE_MULS) {
                float2 t0 = *(const float2*)&tanhT[(size_t)m * Nglob + n];
                float2 t1 = *(const float2*)&tanhT[(size_t)(m + 8) * Nglob + n];
                __nv_bfloat162 h0 = __floats2bfloat162_rn(
                    ac[0] * (1.0f - t0.x * t0.x), ac[1] * (1.0f - t0.y * t0.y));
                __nv_bfloat162 h1 = __floats2bfloat162_rn(
                    ac[2] * (1.0f - t1.x * t1.x), ac[3] * (1.0f - t1.y * t1.y));
                *(__nv_bfloat162*)&Cs[(size_t)m * Nglob + n]       = h0;
                *(__nv_bfloat162*)&Cs[(size_t)(m + 8) * Nglob + n] = h1;
            } else {
                float* Cb = C + (size_t)blockIdx.z * (BATCH * DIM);
                *(float2*)&Cb[(size_t)m * Nglob + n]       = make_float2(ac[0], ac[1]);
                *(float2*)&Cb[(size_t)(m + 8) * Nglob + n] = make_float2(ac[2], ac[3]);
            }
        }
    }
}

// fp32 [R][K] -> split bf16 [R][2K]
__global__ void __launch_bounds__(256)
split_k(const float* __restrict__ in, __nv_bfloat16* __restrict__ outs, int K)
{
    const int e4 = (blockIdx.x * 256 + threadIdx.x) * 4;
    const int row = e4 / K, k = e4 % K;
    float4 v = *(const float4*)&in[e4];
    __nv_bfloat162 h0 = __floats2bfloat162_rn(v.x, v.y);
    __nv_bfloat162 h1 = __floats2bfloat162_rn(v.z, v.w);
    __nv_bfloat162 l0 = __floats2bfloat162_rn(v.x - __bfloat162float(h0.x),
                                              v.y - __bfloat162float(h0.y));
    __nv_bfloat162 l1 = __floats2bfloat162_rn(v.z - __bfloat162float(h1.x),
                                              v.w - __bfloat162float(h1.y));
    *(__nv_bfloat162*)&outs[(size_t)row * 2 * K + k]         = h0;
    *(__nv_bfloat162*)&outs[(size_t)row * 2 * K + k + 2]     = h1;
    *(__nv_bfloat162*)&outs[(size_t)row * 2 * K + K + k]     = l0;
    *(__nv_bfloat162*)&outs[(size_t)row * 2 * K + K + k + 2] = l1;
}

// RMODE 0: fp32 out = sum + bias, plain bf16 outs
// RMODE 1: plain bf16 outs = aux + scale*sum
// RMODE 2: fp32 out = aux + scale*sum
template<int RMODE>
__global__ void __launch_bounds__(256)
reduce_ep(const float* __restrict__ part, const float* __restrict__ aux,
          float scale, float* __restrict__ out, __nv_bfloat16* __restrict__ outs)
{
    const int e4 = (blockIdx.x * 256 + threadIdx.x) * 4;
    float4 s0 = *(const float4*)&part[e4];
    float4 s1 = *(const float4*)&part[BATCH * DIM     + e4];
    float4 s2 = *(const float4*)&part[BATCH * DIM * 2 + e4];
    float4 s3 = *(const float4*)&part[BATCH * DIM * 3 + e4];
    float4 r;
    r.x = (s0.x + s1.x) + (s2.x + s3.x);
    r.y = (s0.y + s1.y) + (s2.y + s3.y);
    r.z = (s0.z + s1.z) + (s2.z + s3.z);
    r.w = (s0.w + s1.w) + (s2.w + s3.w);
    if (RMODE == 0) {
        float4 b = *(const float4*)&aux[e4 & (DIM - 1)];
        r.x += b.x; r.y += b.y; r.z += b.z; r.w += b.w;
    } else {
        float4 b = *(const float4*)&aux[e4];
        r.x = fmaf(scale, r.x, b.x); r.y = fmaf(scale, r.y, b.y);
        r.z = fmaf(scale, r.z, b.z); r.w = fmaf(scale, r.w, b.w);
    }
    if (RMODE == 0 || RMODE == 2)
        *(float4*)&out[e4] = r;
    if (RMODE <= 1) {
        __nv_bfloat162 h0 = __floats2bfloat162_rn(r.x, r.y);
        __nv_bfloat162 h1 = __floats2bfloat162_rn(r.z, r.w);
        *(__nv_bfloat162*)&outs[e4]     = h0;
        *(__nv_bfloat162*)&outs[e4 + 2] = h1;
    }
}

extern "C" void kernel_launch(void* const* d_in, const int* in_sizes, int n_in,
                              void* d_out, int out_size)
{
    const float* y  = (const float*)d_in[0];
    const float* W1 = (const float*)d_in[1];
    const float* b1 = (const float*)d_in[2];
    const float* W2 = (const float*)d_in[3];
    const float* b2 = (const float*)d_in[4];
    float* out = (float*)d_out;

    float *pT, *pV, *pPart;
    __nv_bfloat16 *pYs, *pW1s, *pW2s, *pTs, *pPp, *pVp, *pUp;
    cudaGetSymbolAddress((void**)&pT,    g_T);
    cudaGetSymbolAddress((void**)&pV,    g_V);
    cudaGetSymbolAddress((void**)&pPart, g_part);
    cudaGetSymbolAddress((void**)&pYs,   g_ys);
    cudaGetSymbolAddress((void**)&pW1s,  g_W1s);
    cudaGetSymbolAddress((void**)&pW2s,  g_W2s);
    cudaGetSymbolAddress((void**)&pTs,   g_Ts);
    cudaGetSymbolAddress((void**)&pPp,   g_Pp);
    cudaGetSymbolAddress((void**)&pVp,   g_Vp);
    cudaGetSymbolAddress((void**)&pUp,   g_Up);

    dim3 gL(HID / 64, BATCH / 64, 1);   // 128 CTAs
    dim3 gS(DIM / 64, BATCH / 64, 4);   // 128 CTAs
    const int gR = (BATCH * DIM) / (256 * 4);

    const float c3 = 0.01f / 3.0f;

    // operand splits (W hi-halves double as plain bf16 weights)
    split_k<<<(BATCH * DIM) / 1024, 256>>>(y,  pYs,  DIM);
    split_k<<<(HID * DIM)   / 1024, 256>>>(W1, pW1s, DIM);
    split_k<<<(DIM * HID)   / 1024, 256>>>(W2, pW2s, HID);

    // forward (split precision): T = tanh(y W1^T + b1);  V = T W2^T + b2
    mmagemm<MODE_TANH, 3><<<gL, 256>>>(pYs, 2 * DIM, pW1s, 2 * DIM, DIM,
                                       pT, pTs, HID, b1, nullptr);
    mmagemm<MODE_PART, 3><<<gS, 256>>>(pTs, 2 * HID, pW2s, 2 * HID, HID,
                                       pPart, nullptr, DIM, nullptr, nullptr);
    reduce_ep<0><<<gR, 256>>>(pPart, b2, 0.0f, pV, pVp);

    // u = v + B v   (plain bf16 corrections)
    mmagemm<MODE_MULS, 1><<<gL, 256>>>(pVp, DIM, pW1s, 2 * DIM, 0,
                                       nullptr, pPp, HID, nullptr, pT);
    mmagemm<MODE_PART, 1><<<gS, 256>>>(pPp, HID, pW2s, 2 * HID, 0,
                                       pPart, nullptr, DIM, nullptr, nullptr);
    reduce_ep<1><<<gR, 256>>>(pPart, pV, c3, nullptr, pUp);

    // out = v + 1.5 B u
    mmagemm<MODE_MULS, 1><<<gL, 256>>>(pUp, DIM, pW1s, 2 * DIM, 0,
                                       nullptr, pPp, HID, nullptr, pT);
    mmagemm<MODE_PART, 1><<<gS, 256>>>(pPp, HID, pW2s, 2 * HID, 0,
                                       pPart, nullptr, DIM, nullptr, nullptr);
    reduce_ep<2><<<gR, 256>>>(pPart, pV, 1.5f * c3, out, nullptr);
}

// round 8
// speedup vs baseline: 5.4959x; 1.0131x over previous
#include <cuda_runtime.h>
#include <cuda_bf16.h>
#include <cstdint>
#include <math.h>

// EulerRosenbrockModel: B=512, D=256, HID=1024, H_STEP=0.01
// phi(A)v = v + 1.5 B v + 1.5 B^2 v,  B = (h/3) J  (||B|| ~ 0.015)
// mma.sync bf16 tensor-pipe GEMMs. Forward pass in bf16 double-split
// (hi*hi + hi*lo + lo*hi); correction path plain bf16.
// CTA tile 32x64, grid 256 CTAs, 4-stage cp.async ring (one sync per chunk).

static constexpr int BATCH = 512;
static constexpr int DIM   = 256;
static constexpr int HID   = 1024;

__device__ float g_T   [BATCH * HID];
__device__ float g_V   [BATCH * DIM];
__device__ float g_part[4 * BATCH * DIM];
__device__ __nv_bfloat16 g_ys [BATCH * 2 * DIM];
__device__ __nv_bfloat16 g_W1s[HID   * 2 * DIM];
__device__ __nv_bfloat16 g_W2s[DIM   * 2 * HID];
__device__ __nv_bfloat16 g_Ts [BATCH * 2 * HID];
__device__ __nv_bfloat16 g_Pp [BATCH * HID];
__device__ __nv_bfloat16 g_Vp [BATCH * DIM];
__device__ __nv_bfloat16 g_Up [BATCH * DIM];

// ---------------- low-level helpers ----------------
__device__ __forceinline__ uint32_t smem_u32(const void* p) {
    uint32_t a;
    asm("{ .reg .u64 t; cvta.to.shared.u64 t, %1; cvt.u32.u64 %0, t; }"
        : "=r"(a) : "l"(p));
    return a;
}
__device__ __forceinline__ void cp16(uint32_t dst, const void* src) {
    asm volatile("cp.async.cg.shared.global [%0], [%1], 16;" :: "r"(dst), "l"(src));
}
__device__ __forceinline__ void cp_commit() {
    asm volatile("cp.async.commit_group;" ::: "memory");
}
template<int N>
__device__ __forceinline__ void cp_wait() {
    asm volatile("cp.async.wait_group %0;" :: "n"(N) : "memory");
}
__device__ __forceinline__ void ldm4(uint32_t* r, uint32_t addr) {
    asm volatile("ldmatrix.sync.aligned.m8n8.x4.shared.b16 {%0,%1,%2,%3}, [%4];"
        : "=r"(r[0]), "=r"(r[1]), "=r"(r[2]), "=r"(r[3]) : "r"(addr));
}
__device__ __forceinline__ void mma_bf16(float* d, const uint32_t* a, const uint32_t* b) {
    asm volatile("mma.sync.aligned.m16n8k16.row.col.f32.bf16.bf16.f32 "
        "{%0,%1,%2,%3}, {%4,%5,%6,%7}, {%8,%9}, {%0,%1,%2,%3};"
        : "+f"(d[0]), "+f"(d[1]), "+f"(d[2]), "+f"(d[3])
        : "r"(a[0]), "r"(a[1]), "r"(a[2]), "r"(a[3]), "r"(b[0]), "r"(b[1]));
}
__device__ __forceinline__ void st_split(__nv_bfloat16* Cs, int Kw, int m, int n,
                                         float v0, float v1) {
    __nv_bfloat162 h = __floats2bfloat162_rn(v0, v1);
    float l0 = v0 - __bfloat162float(h.x);
    float l1 = v1 - __bfloat162float(h.y);
    __nv_bfloat162 l = __floats2bfloat162_rn(l0, l1);
    *(__nv_bfloat162*)&Cs[(size_t)m * (2 * Kw) + n]      = h;
    *(__nv_bfloat162*)&Cs[(size_t)m * (2 * Kw) + Kw + n] = l;
}

#define MODE_TANH 0
#define MODE_MULS 1
#define MODE_PART 2

// CTA tile 32x64. 8 warps: wm in {0,1} (16 m-rows), wn in {0..3} (16 n-cols).
// NREG=3: 12 chunks across regions; NREG=1: 4 chunks plain bf16.
// 4-stage cp.async ring (12KB/stage), single __syncthreads per chunk.
template<int MODE, int NREG>
__global__ void __launch_bounds__(256)
mmagemm(const __nv_bfloat16* __restrict__ A, int lda,
        const __nv_bfloat16* __restrict__ Bw, int ldb, int Ka,
        float* __restrict__ C, __nv_bfloat16* __restrict__ Cs,
        int Nglob, const float* __restrict__ bias, const float* __restrict__ tanhT)
{
    constexpr int CHUNKS = 4 * NREG;
    constexpr int STAGE  = 12288;           // 4KB A + 8KB B
    __shared__ __align__(1024) char smem[4 * STAGE];
    const uint32_t sb = smem_u32(smem);

    const int tid = threadIdx.x;
    const int wid = tid >> 5;
    const int lid = tid & 31;
    const int wm  = wid >> 2;               // 0..1
    const int wn  = wid & 3;                // 0..3
    const int m0  = blockIdx.y * 32;
    const int n0  = blockIdx.x * 64;
    const int zoff = blockIdx.z * 256;

    float acc[2][4];
    #pragma unroll
    for (int g = 0; g < 2; g++)
        #pragma unroll
        for (int q = 0; q < 4; q++) acc[g][q] = 0.0f;

    const int m_l = wm * 16 + ((lid >> 3) & 1) * 8 + (lid & 7);
    const int n_l = wn * 16 + (lid >> 4) * 8 + (lid & 7);
    const int a_so = (lid >> 4);
    const int b_so = ((lid >> 3) & 1);
    const uint32_t ax = (uint32_t)((m_l & 7) << 4);
    const uint32_t bx = (uint32_t)((n_l & 7) << 4);

    auto issue = [&](int cc, int st) {
        const int r  = (NREG == 3) ? (cc >> 2) : 0;
        const int kb = (cc & 3) * 64;
        const int ak = zoff + kb + (r == 2 ? Ka : 0);
        const int bk = zoff + kb + (r == 1 ? Ka : 0);
        const uint32_t ab = sb + st * STAGE;
        const uint32_t bb = ab + 4096;
        #pragma unroll
        for (int t = tid; t < 768; t += 256) {
            const int row = (t & 255) >> 3, seg = t & 7;
            const uint32_t sw = (uint32_t)(seg * 16) ^ (uint32_t)((row & 7) << 4);
            if (t < 256) {
                cp16(ab + row * 128 + sw,
                     A + (size_t)(m0 + row) * lda + ak + seg * 8);
            } else {
                const int rr = t >= 512 ? row + 32 : row;
                cp16(bb + rr * 128 + sw,
                     Bw + (size_t)(n0 + rr) * ldb + bk + seg * 8);
            }
        }
    };

    // prologue: 3 stages in flight
    issue(0, 0); cp_commit();
    issue(1, 1); cp_commit();
    if (CHUNKS > 2) { issue(2, 2); cp_commit(); }

    #pragma unroll 1
    for (int c = 0; c < CHUNKS; c++) {
        const int rem = CHUNKS - 1 - c;
        if (rem >= 2)      cp_wait<2>();
        else if (rem == 1) cp_wait<1>();
        else               cp_wait<0>();
        __syncthreads();
        if (c + 3 < CHUNKS) { issue(c + 3, (c + 3) & 3); cp_commit(); }

        const uint32_t ab = sb + (c & 3) * STAGE;
        const uint32_t aRow = ab + m_l * 128;
        const uint32_t bRow = ab + 4096 + n_l * 128;
        #pragma unroll
        for (int k = 0; k < 4; k++) {
            uint32_t a0[4], b[4];
            const uint32_t as = (uint32_t)((k * 2 + a_so) * 16) ^ ax;
            const uint32_t bs = (uint32_t)((k * 2 + b_so) * 16) ^ bx;
            ldm4(a0, aRow + as);
            ldm4(b,  bRow + bs);
            mma_bf16(acc[0], a0, b);
            mma_bf16(acc[1], a0, b + 2);
        }
    }

    // ---- epilogue ----
    const int gid  = lid >> 2;
    const int tid4 = lid & 3;
    #pragma unroll
    for (int g = 0; g < 2; g++) {
        const int m = m0 + wm * 16 + gid;
        const int n = n0 + wn * 16 + g * 8 + tid4 * 2;
        const float* ac = acc[g];
        if (MODE == MODE_TANH) {
            const float b0v = bias[n], b1v = bias[n + 1];
            float v00 = tanhf(ac[0] + b0v), v01 = tanhf(ac[1] + b1v);
            float v10 = tanhf(ac[2] + b0v), v11 = tanhf(ac[3] + b1v);
            *(float2*)&C[(size_t)m * Nglob + n]       = make_float2(v00, v01);
            *(float2*)&C[(size_t)(m + 8) * Nglob + n] = make_float2(v10, v11);
            st_split(Cs, Nglob, m,     n, v00, v01);
            st_split(Cs, Nglob, m + 8, n, v10, v11);
        } else if (MODE == MODE_MULS) {
            float2 t0 = *(const float2*)&tanhT[(size_t)m * Nglob + n];
            float2 t1 = *(const float2*)&tanhT[(size_t)(m + 8) * Nglob + n];
            __nv_bfloat162 h0 = __floats2bfloat162_rn(
                ac[0] * (1.0f - t0.x * t0.x), ac[1] * (1.0f - t0.y * t0.y));
            __nv_bfloat162 h1 = __floats2bfloat162_rn(
                ac[2] * (1.0f - t1.x * t1.x), ac[3] * (1.0f - t1.y * t1.y));
            *(__nv_bfloat162*)&Cs[(size_t)m * Nglob + n]       = h0;
            *(__nv_bfloat162*)&Cs[(size_t)(m + 8) * Nglob + n] = h1;
        } else {
            float* Cb = C + (size_t)blockIdx.z * (BATCH * DIM);
            *(float2*)&Cb[(size_t)m * Nglob + n]       = make_float2(ac[0], ac[1]);
            *(float2*)&Cb[(size_t)(m + 8) * Nglob + n] = make_float2(ac[2], ac[3]);
        }
    }
}

// fused split of y, W1, W2 -> split bf16 panels (one launch)
__global__ void __launch_bounds__(256)
split_all(const float* __restrict__ y, const float* __restrict__ W1,
          const float* __restrict__ W2,
          __nv_bfloat16* __restrict__ ys, __nv_bfloat16* __restrict__ W1s,
          __nv_bfloat16* __restrict__ W2s)
{
    int b = blockIdx.x;
    const float* in;
    __nv_bfloat16* outs;
    int K;
    if (b < 128)      { in = y;  outs = ys;  K = DIM; }
    else if (b < 384) { in = W1; outs = W1s; K = DIM;  b -= 128; }
    else              { in = W2; outs = W2s; K = HID;  b -= 384; }

    const int e4 = (b * 256 + threadIdx.x) * 4;
    const int row = e4 / K, k = e4 % K;
    float4 v = *(const float4*)&in[e4];
    __nv_bfloat162 h0 = __floats2bfloat162_rn(v.x, v.y);
    __nv_bfloat162 h1 = __floats2bfloat162_rn(v.z, v.w);
    __nv_bfloat162 l0 = __floats2bfloat162_rn(v.x - __bfloat162float(h0.x),
                                              v.y - __bfloat162float(h0.y));
    __nv_bfloat162 l1 = __floats2bfloat162_rn(v.z - __bfloat162float(h1.x),
                                              v.w - __bfloat162float(h1.y));
    *(__nv_bfloat162*)&outs[(size_t)row * 2 * K + k]         = h0;
    *(__nv_bfloat162*)&outs[(size_t)row * 2 * K + k + 2]     = h1;
    *(__nv_bfloat162*)&outs[(size_t)row * 2 * K + K + k]     = l0;
    *(__nv_bfloat162*)&outs[(size_t)row * 2 * K + K + k + 2] = l1;
}

// RMODE 0: fp32 out = sum + bias, plain bf16 outs
// RMODE 1: plain bf16 outs = aux + scale*sum
// RMODE 2: fp32 out = aux + scale*sum
template<int RMODE>
__global__ void __launch_bounds__(256)
reduce_ep(const float* __restrict__ part, const float* __restrict__ aux,
          float scale, float* __restrict__ out, __nv_bfloat16* __restrict__ outs)
{
    const int e4 = (blockIdx.x * 256 + threadIdx.x) * 4;
    float4 s0 = *(const float4*)&part[e4];
    float4 s1 = *(const float4*)&part[BATCH * DIM     + e4];
    float4 s2 = *(const float4*)&part[BATCH * DIM * 2 + e4];
    float4 s3 = *(const float4*)&part[BATCH * DIM * 3 + e4];
    float4 r;
    r.x = (s0.x + s1.x) + (s2.x + s3.x);
    r.y = (s0.y + s1.y) + (s2.y + s3.y);
    r.z = (s0.z + s1.z) + (s2.z + s3.z);
    r.w = (s0.w + s1.w) + (s2.w + s3.w);
    if (RMODE == 0) {
        float4 b = *(const float4*)&aux[e4 & (DIM - 1)];
        r.x += b.x; r.y += b.y; r.z += b.z; r.w += b.w;
    } else {
        float4 b = *(const float4*)&aux[e4];
        r.x = fmaf(scale, r.x, b.x); r.y = fmaf(scale, r.y, b.y);
        r.z = fmaf(scale, r.z, b.z); r.w = fmaf(scale, r.w, b.w);
    }
    if (RMODE == 0 || RMODE == 2)
        *(float4*)&out[e4] = r;
    if (RMODE <= 1) {
        __nv_bfloat162 h0 = __floats2bfloat162_rn(r.x, r.y);
        __nv_bfloat162 h1 = __floats2bfloat162_rn(r.z, r.w);
        *(__nv_bfloat162*)&outs[e4]     = h0;
        *(__nv_bfloat162*)&outs[e4 + 2] = h1;
    }
}

extern "C" void kernel_launch(void* const* d_in, const int* in_sizes, int n_in,
                              void* d_out, int out_size)
{
    const float* y  = (const float*)d_in[0];
    const float* W1 = (const float*)d_in[1];
    const float* b1 = (const float*)d_in[2];
    const float* W2 = (const float*)d_in[3];
    const float* b2 = (const float*)d_in[4];
    float* out = (float*)d_out;

    float *pT, *pV, *pPart;
    __nv_bfloat16 *pYs, *pW1s, *pW2s, *pTs, *pPp, *pVp, *pUp;
    cudaGetSymbolAddress((void**)&pT,    g_T);
    cudaGetSymbolAddress((void**)&pV,    g_V);
    cudaGetSymbolAddress((void**)&pPart, g_part);
    cudaGetSymbolAddress((void**)&pYs,   g_ys);
    cudaGetSymbolAddress((void**)&pW1s,  g_W1s);
    cudaGetSymbolAddress((void**)&pW2s,  g_W2s);
    cudaGetSymbolAddress((void**)&pTs,   g_Ts);
    cudaGetSymbolAddress((void**)&pPp,   g_Pp);
    cudaGetSymbolAddress((void**)&pVp,   g_Vp);
    cudaGetSymbolAddress((void**)&pUp,   g_Up);

    dim3 gL(HID / 64, BATCH / 32, 1);   // (16,16,1) = 256 CTAs
    dim3 gS(DIM / 64, BATCH / 32, 4);   // ( 4,16,4) = 256 CTAs
    const int gR = (BATCH * DIM) / (256 * 4);

    const float c3 = 0.01f / 3.0f;

    split_all<<<640, 256>>>(y, W1, W2, pYs, pW1s, pW2s);

    // forward (split precision): T = tanh(y W1^T + b1);  V = T W2^T + b2
    mmagemm<MODE_TANH, 3><<<gL, 256>>>(pYs, 2 * DIM, pW1s, 2 * DIM, DIM,
                                       pT, pTs, HID, b1, nullptr);
    mmagemm<MODE_PART, 3><<<gS, 256>>>(pTs, 2 * HID, pW2s, 2 * HID, HID,
                                       pPart, nullptr, DIM, nullptr, nullptr);
    reduce_ep<0><<<gR, 256>>>(pPart, b2, 0.0f, pV, pVp);

    // u = v + B v   (plain bf16 corrections)
    mmagemm<MODE_MULS, 1><<<gL, 256>>>(pVp, DIM, pW1s, 2 * DIM, 0,
                                       nullptr, pPp, HID, nullptr, pT);
    mmagemm<MODE_PART, 1><<<gS, 256>>>(pPp, HID, pW2s, 2 * HID, 0,
                                       pPart, nullptr, DIM, nullptr, nullptr);
    reduce_ep<1><<<gR, 256>>>(pPart, pV, c3, nullptr, pUp);

    // out = v + 1.5 B u
    mmagemm<MODE_MULS, 1><<<gL, 256>>>(pUp, DIM, pW1s, 2 * DIM, 0,
                                       nullptr, pPp, HID, nullptr, pT);
    mmagemm<MODE_PART, 1><<<gS, 256>>>(pPp, HID, pW2s, 2 * HID, 0,
                                       pPart, nullptr, DIM, nullptr, nullptr);
    reduce_ep<2><<<gR, 256>>>(pPart, pV, 1.5f * c3, out, nullptr);
}